// round 14
// baseline (speedup 1.0000x reference)
#include <cuda_runtime.h>
#include <math.h>

#define TT 256
#define BB 64
#define HH 1024
#define SS 15
#define HB (HH*BB)          // 65536 floats per (H,B) plane
#define NB 256              // persistent grid (2 CTAs/SM x 148 SMs >= 256)

// ------------------------- static device scratch -------------------------
__device__ __align__(16) float g_embT [(size_t)TT*HB];      // (t, h, b)
__device__ __align__(16) float g_parts[(size_t)TT*64*BB];   // parser partials
__device__ __align__(16) float g_mg  [TT*SS*BB];            // (t, s, b)
__device__ __align__(16) float g_mgn [TT*SS*BB];
__device__ __align__(16) float g_mh  [2*SS*HB];             // rings (layer, slot, h, b)
__device__ __align__(16) float g_mc  [2*SS*HB];
__device__ __align__(16) float g_pm  [SS*HB];
__device__ __align__(16) float g_h1  [HB];
__device__ __align__(16) float g_h2  [HB];
__device__ __align__(16) float g_key [HB];
__device__ __align__(16) float g_lp  [60*64];               // logits partials (s*4+c, b)
__device__ __align__(16) float g_selh[HB];
__device__ __align__(16) float g_selc[HB];
__device__ __align__(16) float g_partk[16*HB];              // reader/key partials
__device__ __align__(16) float g_partp[16*HB];              // predictor key partials
__device__ __align__(16) float g_partg[6*4096*64];          // gates partials (p0,1 wih; p2..5 whh)
__device__ __align__(16) float g_hs  [(size_t)TT*HB];
__device__ __align__(16) float g_sels[(size_t)TT*HB];

__device__ unsigned g_bar;     // global barrier counter (256 arrivals/epoch)
__device__ unsigned g_abar;    // attention sub-barrier (64 arrivals/epoch)

__device__ __forceinline__ float sigm(float x){ return 1.f/(1.f+expf(-x)); }

#define ADD4(a, v) { (a).x += (v).x; (a).y += (v).y; (a).z += (v).z; (a).w += (v).w; }
#define FMA4(a, s, v) { (a).x += (s)*(v).x; (a).y += (s)*(v).y; (a).z += (s)*(v).z; (a).w += (s)*(v).w; }

__device__ __forceinline__ float4 ldcg4(const float* p){ return __ldcg((const float4*)p); }
__device__ __forceinline__ void   stcg4(float* p, float4 v){ __stcg((float4*)p, v); }

// ------------------------- barriers (fence-free, .cg data discipline) ---------
__device__ __forceinline__ void gridbar(unsigned ep)
{
    __syncthreads();
    if (threadIdx.x == 0) {
        asm volatile("red.release.gpu.global.add.u32 [%0], 1;" :: "l"(&g_bar) : "memory");
        unsigned tgt = ep * NB, v;
        asm volatile("ld.acquire.gpu.global.u32 %0, [%1];" : "=r"(v) : "l"(&g_bar) : "memory");
        while (v < tgt) {
            __nanosleep(96);
            asm volatile("ld.acquire.gpu.global.u32 %0, [%1];" : "=r"(v) : "l"(&g_bar) : "memory");
        }
    }
    __syncthreads();
}

__device__ __forceinline__ void abar(unsigned aep)   // blocks 0..63 only
{
    __syncthreads();
    if (threadIdx.x == 0) {
        asm volatile("red.release.gpu.global.add.u32 [%0], 1;" :: "l"(&g_abar) : "memory");
        unsigned tgt = aep * 64, v;
        asm volatile("ld.acquire.gpu.global.u32 %0, [%1];" : "=r"(v) : "l"(&g_abar) : "memory");
        while (v < tgt) {
            __nanosleep(64);
            asm volatile("ld.acquire.gpu.global.u32 %0, [%1];" : "=r"(v) : "l"(&g_abar) : "memory");
        }
    }
    __syncthreads();
}

// ------------------------- embedding gather + transpose + ring zero ------------
__global__ void __launch_bounds__(256) k_embzero(const int* __restrict__ tok,
                                                 const float* __restrict__ table)
{
    int t = blockIdx.x, tid = threadIdx.x;
    __shared__ float sm[64][65];
    __shared__ int stok[64];
    if (tid < 64) stok[tid] = tok[t*64 + tid];
    __syncthreads();
    for (int kc = 0; kc < HH; kc += 64) {
        for (int i = tid; i < 4096; i += 256) {
            int b = i >> 6, j = i & 63;
            sm[j][b] = table[(size_t)stok[b]*HH + kc + j];
        }
        __syncthreads();
        for (int i = tid; i < 4096; i += 256) {
            int j = i >> 6, b = i & 63;
            g_embT[((size_t)t*HH + kc + j)*64 + b] = sm[j][b];
        }
        __syncthreads();
    }
    // ring zero + barrier reset
    float4 z = make_float4(0.f,0.f,0.f,0.f);
    int gtid = blockIdx.x*256 + tid;                    // 65536 threads
    for (int i = gtid; i < 2*SS*HB/4; i += 65536) {
        ((float4*)g_mh)[i] = z;
        ((float4*)g_mc)[i] = z;
    }
    for (int i = gtid; i < SS*HB/4; i += 65536)
        ((float4*)g_pm)[i] = z;
    if (gtid == 0) { g_bar = 0u; g_abar = 0u; }
}

// ------------------------- parser conv1+bn+relu+conv2 partials -------------------------
__global__ void __launch_bounds__(256) k_parser(const float* __restrict__ w1,
        const float* __restrict__ c1b, const float* __restrict__ bng,
        const float* __restrict__ bnb, const float* __restrict__ w2)
{
    int chunk = blockIdx.x;
    int t     = blockIdx.y;
    int tx = threadIdx.x, ty = threadIdx.y;
    int tid = ty*64 + tx;
    int obase = chunk*16;
    __shared__ float e0s[4096], e1s[4096];
    __shared__ float2 ws[1024];
    __shared__ float red[4][64];
    float acc0=0.f, acc1=0.f, acc2=0.f, acc3=0.f;
    const float* s1 = &g_embT[(size_t)t*HB];
    const float* s0 = (t > 0) ? &g_embT[(size_t)(t-1)*HB] : 0;
    const float2* wv = (const float2*)w1;
    for (int kt = 0; kt < HH; kt += 64) {
        for (int i = tid; i < 4096; i += 256) {
            e1s[i] = s1[kt*64 + i];
            e0s[i] = s0 ? s0[kt*64 + i] : 0.f;
        }
        for (int i = tid; i < 1024; i += 256) {
            int o = i >> 6, k = i & 63;
            ws[i] = wv[(size_t)(obase+o)*HH + kt + k];
        }
        __syncthreads();
        #pragma unroll 8
        for (int k = 0; k < 64; k++) {
            float e0 = e0s[k*64 + tx];
            float e1 = e1s[k*64 + tx];
            float2 wa = ws[(ty*4+0)*64 + k];
            float2 wb = ws[(ty*4+1)*64 + k];
            float2 wc = ws[(ty*4+2)*64 + k];
            float2 wd = ws[(ty*4+3)*64 + k];
            acc0 += wa.x*e0 + wa.y*e1;
            acc1 += wb.x*e0 + wb.y*e1;
            acc2 += wc.x*e0 + wc.y*e1;
            acc3 += wd.x*e0 + wd.y*e1;
        }
        __syncthreads();
    }
    float part = 0.f;
    {
        int o0 = obase + ty*4;
        float v;
        v = bng[o0+0]*(acc0 + c1b[o0+0]) + bnb[o0+0]; part += w2[o0+0]*fmaxf(v, 0.f);
        v = bng[o0+1]*(acc1 + c1b[o0+1]) + bnb[o0+1]; part += w2[o0+1]*fmaxf(v, 0.f);
        v = bng[o0+2]*(acc2 + c1b[o0+2]) + bnb[o0+2]; part += w2[o0+2]*fmaxf(v, 0.f);
        v = bng[o0+3]*(acc3 + c1b[o0+3]) + bnb[o0+3]; part += w2[o0+3]*fmaxf(v, 0.f);
    }
    red[ty][tx] = part;
    __syncthreads();
    if (ty == 0)
        g_parts[((size_t)t*64 + chunk)*64 + tx] =
            red[0][tx] + red[1][tx] + red[2][tx] + red[3][tx];
}

// ------------------------- gates + masks (fused) -------------------------
__global__ void __launch_bounds__(256) k_gatemask(const float* __restrict__ c2b)
{
    int idx = blockIdx.x*256 + threadIdx.x;   // grid 64 -> (t,b)
    int t = idx >> 6, b = idx & 63;
    float c0 = c2b[0], c1 = c2b[1];
    float s1 = 0.f;
    for (int c = 32; c < 64; c++) s1 += g_parts[((size_t)t*64 + c)*64 + b];
    float gn = sigm(s1 + c1);
    float g0 = 0.f, cm = 1.f, cmn = 1.f;
    for (int s = 0; s < SS; s++) {
        float gh;
        if (t - s >= 0) {
            float s0 = 0.f;
            for (int c = 0; c < 32; c++) s0 += g_parts[((size_t)(t-s)*64 + c)*64 + b];
            gh = sigm(s0 + c0);
        } else gh = 1e8f;
        if (s == 0) g0 = gh;
        cm  *= sigm((g0 - gh)*100.f + 5.f);
        cmn *= sigm((gn - gh)*100.f + 5.f);
        g_mg [((size_t)t*SS + s)*64 + b] = cm;
        g_mgn[((size_t)t*SS + s)*64 + b] = cmn;
    }
}

// ------------------------- GEMM tile (scalar FMA + reg prefetch, X via .cg) ----------
__device__ __forceinline__ void gemm_tile(const float* __restrict__ W, int wstride,
    const float* __restrict__ X, float* __restrict__ part,
    int ob0, int k0, int klen, float* s_x, float* s_w)
{
    int tid = threadIdx.x;
    int og = tid >> 4, bq = tid & 15;
    int r0 = tid >> 3, c0 = (tid & 7)*4;
    int r1 = (tid + 256) >> 3;
    float4 a0 = make_float4(0,0,0,0), a1 = a0, a2 = a0, a3 = a0;

    const float* Xp = X + (size_t)k0*64;
    float4 px0 = ldcg4(Xp + tid*4);
    float4 px1 = ldcg4(Xp + (tid + 256)*4);
    float4 pw0 = *(const float4*)&W[(size_t)(ob0+r0)*wstride + k0 + c0];   // L1-cached
    float4 pw1 = *(const float4*)&W[(size_t)(ob0+r1)*wstride + k0 + c0];

    for (int kt = 0; kt < klen; kt += 32) {
        ((float4*)s_x)[tid]       = px0;
        ((float4*)s_x)[tid + 256] = px1;
        ((float4*)s_w)[tid]       = pw0;
        ((float4*)s_w)[tid + 256] = pw1;
        __syncthreads();
        if (kt + 32 < klen) {
            const float* Xn = X + (size_t)(k0 + kt + 32)*64;
            px0 = ldcg4(Xn + tid*4);
            px1 = ldcg4(Xn + (tid + 256)*4);
            pw0 = *(const float4*)&W[(size_t)(ob0+r0)*wstride + k0 + kt + 32 + c0];
            pw1 = *(const float4*)&W[(size_t)(ob0+r1)*wstride + k0 + kt + 32 + c0];
        }
        #pragma unroll
        for (int kg = 0; kg < 8; kg++) {
            float4 xv0 = *(float4*)&s_x[(kg*4+0)*64 + bq*4];
            float4 xv1 = *(float4*)&s_x[(kg*4+1)*64 + bq*4];
            float4 xv2 = *(float4*)&s_x[(kg*4+2)*64 + bq*4];
            float4 xv3 = *(float4*)&s_x[(kg*4+3)*64 + bq*4];
            float4 wv0 = *(float4*)&s_w[(og*4+0)*32 + kg*4];
            float4 wv1 = *(float4*)&s_w[(og*4+1)*32 + kg*4];
            float4 wv2 = *(float4*)&s_w[(og*4+2)*32 + kg*4];
            float4 wv3 = *(float4*)&s_w[(og*4+3)*32 + kg*4];
            FMA4(a0, wv0.x, xv0) FMA4(a0, wv0.y, xv1) FMA4(a0, wv0.z, xv2) FMA4(a0, wv0.w, xv3)
            FMA4(a1, wv1.x, xv0) FMA4(a1, wv1.y, xv1) FMA4(a1, wv1.z, xv2) FMA4(a1, wv1.w, xv3)
            FMA4(a2, wv2.x, xv0) FMA4(a2, wv2.y, xv1) FMA4(a2, wv2.z, xv2) FMA4(a2, wv2.w, xv3)
            FMA4(a3, wv3.x, xv0) FMA4(a3, wv3.y, xv1) FMA4(a3, wv3.z, xv2) FMA4(a3, wv3.w, xv3)
        }
        __syncthreads();
    }
    stcg4(&part[(size_t)(ob0 + og*4 + 0)*64 + bq*4], a0);
    stcg4(&part[(size_t)(ob0 + og*4 + 1)*64 + bq*4], a1);
    stcg4(&part[(size_t)(ob0 + og*4 + 2)*64 + bq*4], a2);
    stcg4(&part[(size_t)(ob0 + og*4 + 3)*64 + bq*4], a3);
}

// ------------------------- attention chain (blocks 0..63, 2 sub-barriers) ----------
// combine(partials->g_key) | logits partials | softmax+select (+optional pm update)
__device__ __forceinline__ void attn_chain(
    const float* memh, const float* memc, const float* __restrict__ mask,
    int tc, const float* partbuf, int npart, const float* __restrict__ bias,
    float* outh, float* outc, int pmupd,
    float* s_buf, float* s_att, unsigned* aep)
{
    int tid = threadIdx.x, blk = blockIdx.x;
    // A1: combine
    {
        int f = blk*256 + tid;                       // f4 idx 0..16383
        float4 s = make_float4(0,0,0,0);
        for (int p = 0; p < npart; p++) {
            float4 v = ldcg4(partbuf + (size_t)p*65536 + f*4);
            ADD4(s, v);
        }
        float bi = bias[f >> 4];
        s.x += bi; s.y += bi; s.z += bi; s.w += bi;
        stcg4(g_key + f*4, s);
    }
    abar(++(*aep));
    // A2: logits partials (60 blocks: slot s, h-chunk c of 256)
    if (blk < 60) {
        int s = blk >> 2, c = blk & 3;
        int phys = (tc + s) % SS;
        const float* m = memh + (size_t)phys*HB;
        int bq = tid & 15, hg = tid >> 4;
        float4 acc = make_float4(0,0,0,0);
        int h0 = c*256 + hg*16;
        #pragma unroll 4
        for (int h = h0; h < h0 + 16; h++) {
            float4 mv = ldcg4(m + h*64 + bq*4);
            float4 kv = ldcg4(g_key + h*64 + bq*4);
            acc.x += mv.x*kv.x; acc.y += mv.y*kv.y; acc.z += mv.z*kv.z; acc.w += mv.w*kv.w;
        }
        ((float4*)s_buf)[hg*16 + bq] = acc;
        __syncthreads();
        if (hg == 0) {
            float4 st = make_float4(0,0,0,0);
            #pragma unroll
            for (int g = 0; g < 16; g++) {
                float4 v = ((float4*)s_buf)[g*16 + bq];
                ADD4(st, v);
            }
            st.x *= 0.03125f; st.y *= 0.03125f; st.z *= 0.03125f; st.w *= 0.03125f;
            stcg4(g_lp + (s*4 + c)*64 + bq*4, st);
        }
    }
    abar(++(*aep));
    // A3: local softmax + select over this block's 16 h-rows
    if (tid < 64) {
        float lg[SS]; float mx = -1e30f;
        #pragma unroll
        for (int s = 0; s < SS; s++) {
            float v = __ldcg(&g_lp[(s*4+0)*64 + tid]) + __ldcg(&g_lp[(s*4+1)*64 + tid])
                    + __ldcg(&g_lp[(s*4+2)*64 + tid]) + __ldcg(&g_lp[(s*4+3)*64 + tid]);
            lg[s] = v; mx = fmaxf(mx, v);
        }
        float sum = 0.f;
        #pragma unroll
        for (int s = 0; s < SS; s++) {
            float e = expf(lg[s] - mx) * mask[s*64 + tid];
            s_att[s*64 + tid] = e; sum += e;
        }
        float inv = 1.f/(sum + 1e-8f);
        #pragma unroll
        for (int s = 0; s < SS; s++) s_att[s*64 + tid] *= inv;
    }
    __syncthreads();
    int b = tid & 63, hi = tid >> 6;
    int p0 = tc % SS;
    #pragma unroll
    for (int r = 0; r < 4; r++) {
        int h = blk*16 + r*4 + hi;
        float sh = 0.f, sc = 0.f;
        int p = p0;
        #pragma unroll
        for (int s = 0; s < SS; s++) {
            float a = s_att[s*64 + b];
            sh += a * __ldcg(&memh[(size_t)p*HB + h*64 + b]);
            if (memc) sc += a * __ldcg(&memc[(size_t)p*HB + h*64 + b]);
            p++; if (p == SS) p = 0;
        }
        __stcg(&outh[h*64 + b], sh);
        if (outc) __stcg(&outc[h*64 + b], sc);
        if (pmupd) __stcg(&g_pm[(size_t)p0*HB + h*64 + b], __ldcg(&g_h2[h*64 + b]));
    }
}

// ------------------------- LSTM cell (blocks 0..63), 6 gate partials ------------
__device__ __forceinline__ void cell_block(const float* __restrict__ bih,
        const float* __restrict__ bhh, float* __restrict__ mh, float* __restrict__ mc,
        int slot, float* __restrict__ hout, float* __restrict__ hsout, int blk)
{
    int e4 = blk*256 + threadIdx.x;       // float4 idx 0..16383
    int h  = (e4*4) >> 6;
    int b4 = e4 & 15;
    float4 ig = make_float4(0,0,0,0), fg = ig, gg = ig, og = ig;
    #pragma unroll
    for (int p = 0; p < 6; p++) {
        const float* P = g_partg + (size_t)p*(4096*64);
        float4 v;
        v = ldcg4(P + ((       h)*16 + b4)*4); ADD4(ig, v);
        v = ldcg4(P + ((1024 + h)*16 + b4)*4); ADD4(fg, v);
        v = ldcg4(P + ((2048 + h)*16 + b4)*4); ADD4(gg, v);
        v = ldcg4(P + ((3072 + h)*16 + b4)*4); ADD4(og, v);
    }
    float bi = bih[h]        + bhh[h];
    float bf = bih[1024 + h] + bhh[1024 + h];
    float bg = bih[2048 + h] + bhh[2048 + h];
    float bo = bih[3072 + h] + bhh[3072 + h];
    float4 sc = ldcg4(&g_selc[e4*4]);
    float4 c4, h4;
    c4.x = sigm(fg.x + bf)*sc.x + sigm(ig.x + bi)*tanhf(gg.x + bg);
    c4.y = sigm(fg.y + bf)*sc.y + sigm(ig.y + bi)*tanhf(gg.y + bg);
    c4.z = sigm(fg.z + bf)*sc.z + sigm(ig.z + bi)*tanhf(gg.z + bg);
    c4.w = sigm(fg.w + bf)*sc.w + sigm(ig.w + bi)*tanhf(gg.w + bg);
    h4.x = sigm(og.x + bo)*tanhf(c4.x);
    h4.y = sigm(og.y + bo)*tanhf(c4.y);
    h4.z = sigm(og.z + bo)*tanhf(c4.z);
    h4.w = sigm(og.w + bo)*tanhf(c4.w);
    stcg4(mh + (size_t)slot*HB + e4*4, h4);
    stcg4(mc + (size_t)slot*HB + e4*4, c4);
    stcg4(hout + e4*4, h4);
    if (hsout) stcg4(hsout + e4*4, h4);
}

// ------------------------- persistent scan (9 global barriers / step) -------------
__global__ void __launch_bounds__(256, 2) k_scan(
    const float* __restrict__ wih, const float* __restrict__ whh,
    const float* __restrict__ bih, const float* __restrict__ bhh,
    const float* __restrict__ sw,  const float* __restrict__ sb,
    const float* __restrict__ pw,  const float* __restrict__ pb)
{
    __shared__ __align__(16) float s_x[2048];
    __shared__ __align__(16) float s_w[2048];
    __shared__ float s_att[SS*64];
    int blk = blockIdx.x;
    unsigned ep = 0, aep = 0;

    #pragma unroll 1
    for (int t = 0; t < TT; t++) {
        int slot = t % SS, prev = (t + SS - 1) % SS;
        const float* x0 = g_embT + (size_t)t*HB;

        // G1: attnP(t-1) [0,64) || key0 GEMM [64,128) || wih0 GEMM [128,256)
        if (blk < 64) {
            if (t > 0)
                attn_chain(g_pm, (const float*)0, g_mgn + (size_t)(t-1)*SS*64, t-1,
                           g_partp, 16, pb, g_sels + (size_t)(t-1)*HB, (float*)0, 1,
                           s_x, s_att, &aep);
        } else if (blk < 128) {
            int idx = blk - 64;                      // key0: 16o x 4k, K=512
            int ob0 = (idx >> 2)*64, kg = idx & 3;
            const float* W = sw; const float* X; int k0;
            if (kg < 2) { X = x0; k0 = kg*512; }
            else { W = sw + 1024; X = g_mh + (size_t)prev*HB; k0 = (kg-2)*512; }
            gemm_tile(W, 2048, X, g_partk + (size_t)kg*HB, ob0, k0, 512, s_x, s_w);
        } else {
            int idx = blk - 128;                     // wih0: 64o x 2k, K=512
            int ob0 = (idx >> 1)*64, kg = idx & 1;
            gemm_tile(wih, 1024, x0, g_partg + (size_t)kg*(4096*64), ob0, kg*512, 512, s_x, s_w);
        }
        gridbar(++ep);

        // G2: attn0 [0,64) || key1 mh-half [64,192)
        if (blk < 64) {
            attn_chain(g_mh, g_mc, g_mg + (size_t)t*SS*64, t,
                       g_partk, 4, sb, g_selh, g_selc, 0, s_x, s_att, &aep);
        } else if (blk < 192) {
            int idx = blk - 64;                      // 16o x 8k, K=128
            int ob0 = (idx >> 3)*64, kg = idx & 7;
            gemm_tile(sw + (size_t)HH*2048 + 1024, 2048, g_mh + (size_t)SS*HB + (size_t)prev*HB,
                      g_partk + (size_t)(8+kg)*HB, ob0, kg*128, 128, s_x, s_w);
        }
        gridbar(++ep);

        // G3: whh0 (all 256: 64o x 4k, K=256)
        {
            int ob0 = (blk >> 2)*64, kg = blk & 3;
            gemm_tile(whh, 1024, g_selh, g_partg + (size_t)(2+kg)*(4096*64),
                      ob0, kg*256, 256, s_x, s_w);
        }
        gridbar(++ep);

        // G4: cell0
        if (blk < 64) cell_block(bih, bhh, g_mh, g_mc, slot, g_h1, (float*)0, blk);
        gridbar(++ep);

        // G5: key1 x0-half [0,128) || wih1 [128,256)
        if (blk < 128) {
            int ob0 = (blk >> 3)*64, kg = blk & 7;   // 16o x 8k, K=128, X=g_h1
            gemm_tile(sw + (size_t)HH*2048, 2048, g_h1, g_partk + (size_t)kg*HB,
                      ob0, kg*128, 128, s_x, s_w);
        } else {
            int idx = blk - 128;                     // wih1: 64o x 2k, K=512
            int ob0 = (idx >> 1)*64, kg = idx & 1;
            gemm_tile(wih + (size_t)4096*1024, 1024, g_h1,
                      g_partg + (size_t)kg*(4096*64), ob0, kg*512, 512, s_x, s_w);
        }
        gridbar(++ep);

        // G6: attn1 [0,64) || predkey pm-half [64,192)
        if (blk < 64) {
            attn_chain(g_mh + (size_t)SS*HB, g_mc + (size_t)SS*HB, g_mg + (size_t)t*SS*64, t,
                       g_partk, 16, sb + HH, g_selh, g_selc, 0, s_x, s_att, &aep);
        } else if (blk < 192) {
            int idx = blk - 64;
            int ob0 = (idx >> 3)*64, kg = idx & 7;
            gemm_tile(pw + 1024, 2048, g_pm + (size_t)prev*HB,
                      g_partp + (size_t)(8+kg)*HB, ob0, kg*128, 128, s_x, s_w);
        }
        gridbar(++ep);

        // G7: whh1 (all 256)
        {
            int ob0 = (blk >> 2)*64, kg = blk & 3;
            gemm_tile(whh + (size_t)4096*1024, 1024, g_selh,
                      g_partg + (size_t)(2+kg)*(4096*64), ob0, kg*256, 256, s_x, s_w);
        }
        gridbar(++ep);

        // G8: cell1
        if (blk < 64) cell_block(bih + 4096, bhh + 4096, g_mh + (size_t)SS*HB,
                                 g_mc + (size_t)SS*HB, slot, g_h2,
                                 g_hs + (size_t)t*HB, blk);
        gridbar(++ep);

        // G9: predkey h2-half [0,128)
        if (blk < 128) {
            int ob0 = (blk >> 3)*64, kg = blk & 7;
            gemm_tile(pw, 2048, g_h2, g_partp + (size_t)kg*HB, ob0, kg*128, 128, s_x, s_w);
        }
        gridbar(++ep);
    }
    // final predictor attention for t = TT-1
    if (blk < 64)
        attn_chain(g_pm, (const float*)0, g_mgn + (size_t)(TT-1)*SS*64, TT-1,
                   g_partp, 16, pb, g_sels + (size_t)(TT-1)*HB, (float*)0, 1,
                   s_x, s_att, &aep);
}

// ------------------------- final FFD GEMM + tanh + transpose store -------------------------
__global__ void __launch_bounds__(256) k_ffd(const float* __restrict__ W,
        const float* __restrict__ fb, const float* __restrict__ gma,
        const float* __restrict__ bta, float* __restrict__ out)
{
    __shared__ __align__(16) float xs[2048];
    __shared__ __align__(16) float ws[2048];
    __shared__ __align__(16) float tile[4096];
    int ob0 = blockIdx.x*64;
    int t   = blockIdx.y;
    int tid = threadIdx.x;
    int og = tid >> 4, bq = tid & 15;
    const float* xh = &g_hs  [(size_t)t*HB];
    const float* x2 = &g_sels[(size_t)t*HB];
    float4 a0 = make_float4(0,0,0,0), a1 = a0, a2 = a0, a3 = a0;
    for (int kt = 0; kt < 2048; kt += 32) {
        const float* X = (kt < 1024) ? xh + kt*64 : x2 + (kt - 1024)*64;
        const float4* Xt = (const float4*)X;
        ((float4*)xs)[tid]       = Xt[tid];
        ((float4*)xs)[tid + 256] = Xt[tid + 256];
        #pragma unroll
        for (int r = 0; r < 2; r++) {
            int li = tid + r*256;
            int row = li >> 3, c4 = li & 7;
            ((float4*)ws)[li] = *(const float4*)&W[(size_t)(ob0+row)*2048 + kt + c4*4];
        }
        __syncthreads();
        #pragma unroll
        for (int kg = 0; kg < 8; kg++) {
            float4 xv0 = *(float4*)&xs[(kg*4+0)*64 + bq*4];
            float4 xv1 = *(float4*)&xs[(kg*4+1)*64 + bq*4];
            float4 xv2 = *(float4*)&xs[(kg*4+2)*64 + bq*4];
            float4 xv3 = *(float4*)&xs[(kg*4+3)*64 + bq*4];
            float4 wv0 = *(float4*)&ws[(og*4+0)*32 + kg*4];
            float4 wv1 = *(float4*)&ws[(og*4+1)*32 + kg*4];
            float4 wv2 = *(float4*)&ws[(og*4+2)*32 + kg*4];
            float4 wv3 = *(float4*)&ws[(og*4+3)*32 + kg*4];
            FMA4(a0, wv0.x, xv0) FMA4(a0, wv0.y, xv1) FMA4(a0, wv0.z, xv2) FMA4(a0, wv0.w, xv3)
            FMA4(a1, wv1.x, xv0) FMA4(a1, wv1.y, xv1) FMA4(a1, wv1.z, xv2) FMA4(a1, wv1.w, xv3)
            FMA4(a2, wv2.x, xv0) FMA4(a2, wv2.y, xv1) FMA4(a2, wv2.z, xv2) FMA4(a2, wv2.w, xv3)
            FMA4(a3, wv3.x, xv0) FMA4(a3, wv3.y, xv1) FMA4(a3, wv3.z, xv2) FMA4(a3, wv3.w, xv3)
        }
        __syncthreads();
    }
    float4 accs[4] = {a0, a1, a2, a3};
    #pragma unroll
    for (int i = 0; i < 4; i++) {
        int o = ob0 + og*4 + i;
        float g_ = gma[o], be = bta[o], bi = fb[o];
        float4 a = accs[i];
        a.x = tanhf(g_*(a.x + bi) + be);
        a.y = tanhf(g_*(a.y + bi) + be);
        a.z = tanhf(g_*(a.z + bi) + be);
        a.w = tanhf(g_*(a.w + bi) + be);
        *(float4*)&tile[(og*4+i)*64 + bq*4] = a;
    }
    __syncthreads();
    for (int r = 0; r < 16; r++) {
        int idx = r*256 + tid;
        int bb2 = idx >> 6, oo = idx & 63;
        out[((size_t)(t*64 + bb2))*HH + ob0 + oo] = tile[oo*64 + bb2];
    }
}

// ------------------------- mask tail of output -------------------------
__global__ void k_maskf(const int* __restrict__ tok, float* __restrict__ dst, int rem)
{
    for (int i = blockIdx.x*256 + threadIdx.x; i < rem; i += gridDim.x*256)
        dst[i] = (i < TT*BB) ? (tok[i] != 0 ? 1.f : 0.f) : 0.f;
}
__global__ void k_maskb(const int* __restrict__ tok, unsigned char* __restrict__ dst)
{
    int i = blockIdx.x*256 + threadIdx.x;
    if (i < TT*BB) dst[i] = (tok[i] != 0) ? 1 : 0;
}

// ------------------------- launch -------------------------
extern "C" void kernel_launch(void* const* d_in, const int* in_sizes, int n_in,
                              void* d_out, int out_size)
{
    const int*   tokens = (const int*)  d_in[0];
    const float* embt   = (const float*)d_in[1];
    const float* c1w = (const float*)d_in[2];
    const float* c1b = (const float*)d_in[3];
    const float* bng = (const float*)d_in[4];
    const float* bnb = (const float*)d_in[5];
    const float* c2w = (const float*)d_in[6];
    const float* c2b = (const float*)d_in[7];
    const float* wih = (const float*)d_in[8];
    const float* whh = (const float*)d_in[9];
    const float* bih = (const float*)d_in[10];
    const float* bhh = (const float*)d_in[11];
    const float* sw  = (const float*)d_in[12];
    const float* sb  = (const float*)d_in[13];
    const float* pw  = (const float*)d_in[14];
    const float* pb  = (const float*)d_in[15];
    const float* fw  = (const float*)d_in[16];
    const float* fb  = (const float*)d_in[17];
    const float* fg  = (const float*)d_in[18];
    const float* fbe = (const float*)d_in[19];
    float* out = (float*)d_out;

    k_embzero<<<TT, 256>>>(tokens, embt);
    k_parser<<<dim3(64, TT), dim3(64, 4)>>>(c1w, c1b, bng, bnb, c2w);
    k_gatemask<<<64, 256>>>(c2b);

    // single persistent node for the whole 256-step recurrence (launch #4)
    k_scan<<<NB, 256>>>(wih, whh, bih, bhh, sw, sb, pw, pb);

    k_ffd<<<dim3(16, TT), 256>>>(fw, fb, fg, fbe, out);

    int rem = out_size - TT*BB*HH;
    if (rem > 0) {
        if (rem == TT*BB/4)
            k_maskb<<<64, 256>>>(tokens, (unsigned char*)out + (size_t)TT*BB*HH*4);
        else
            k_maskf<<<64, 256>>>(tokens, out + (size_t)TT*BB*HH, rem);
    }
}

// round 15
// speedup vs baseline: 1.1047x; 1.1047x over previous
#include <cuda_runtime.h>
#include <math.h>

#define TT 256
#define BB 64
#define HH 1024
#define SS 15
#define HB (HH*BB)          // 65536 floats per (H,B) plane
#define NB 256              // persistent grid (2 CTAs/SM x 148 SMs >= 256)

// ------------------------- static device scratch -------------------------
__device__ __align__(16) float g_embT [(size_t)TT*HB];      // (t, h, b)
__device__ __align__(16) float g_parts[(size_t)TT*64*BB];   // parser partials
__device__ __align__(16) float g_mg  [TT*SS*BB];            // (t, s, b)
__device__ __align__(16) float g_mgn [TT*SS*BB];
__device__ __align__(16) float g_mh  [2*SS*HB];             // rings (layer, slot, h, b)
__device__ __align__(16) float g_mc  [2*SS*HB];
__device__ __align__(16) float g_pm  [SS*HB];
__device__ __align__(16) float g_h1  [HB];
__device__ __align__(16) float g_h2  [HB];
__device__ __align__(16) float g_key [HB];
__device__ __align__(16) float g_lp  [60*64];               // logits partials (s*4+c, b)
__device__ __align__(16) float g_selh[HB];
__device__ __align__(16) float g_selc[HB];
__device__ __align__(16) float g_partk[16*HB];              // key GEMM partials (ksplit=16)
__device__ __align__(16) float g_partg[4*4096*64];          // gates GEMM partials (ksplit=4)
__device__ __align__(16) float g_hs  [(size_t)TT*HB];
__device__ __align__(16) float g_sels[(size_t)TT*HB];

__device__ unsigned g_bar;     // global barrier counter

__device__ __forceinline__ float sigm(float x){ return 1.f/(1.f+expf(-x)); }

#define ADD4(a, v) { (a).x += (v).x; (a).y += (v).y; (a).z += (v).z; (a).w += (v).w; }
#define FMA4(a, s, v) { (a).x += (s)*(v).x; (a).y += (s)*(v).y; (a).z += (s)*(v).z; (a).w += (s)*(v).w; }
// packed fp32x2 FMA (SASS FFMA2): IEEE fp32 per lane, bit-identical to scalar (proven R12)
#define FMA2(acc, w, x) asm("fma.rn.f32x2 %0, %1, %2, %0;" : "+l"(acc) : "l"(w), "l"(x))

__device__ __forceinline__ float4 ldcg4(const float* p){ return __ldcg((const float4*)p); }
__device__ __forceinline__ void   stcg4(float* p, float4 v){ __stcg((float4*)p, v); }

// ------------------------- grid barrier (fence-free, .cg data discipline) ---------
__device__ __forceinline__ void gridbar(unsigned ep)
{
    __syncthreads();
    if (threadIdx.x == 0) {
        asm volatile("red.release.gpu.global.add.u32 [%0], 1;" :: "l"(&g_bar) : "memory");
        unsigned tgt = ep * NB, v;
        asm volatile("ld.acquire.gpu.global.u32 %0, [%1];" : "=r"(v) : "l"(&g_bar) : "memory");
        while (v < tgt) {
            __nanosleep(64);
            asm volatile("ld.acquire.gpu.global.u32 %0, [%1];" : "=r"(v) : "l"(&g_bar) : "memory");
        }
    }
    __syncthreads();
}

// ------------------------- embedding gather + transpose + ring zero ------------
__global__ void __launch_bounds__(256) k_embzero(const int* __restrict__ tok,
                                                 const float* __restrict__ table)
{
    int t = blockIdx.x, tid = threadIdx.x;
    __shared__ float sm[64][65];
    __shared__ int stok[64];
    if (tid < 64) stok[tid] = tok[t*64 + tid];
    __syncthreads();
    for (int kc = 0; kc < HH; kc += 64) {
        for (int i = tid; i < 4096; i += 256) {
            int b = i >> 6, j = i & 63;
            sm[j][b] = table[(size_t)stok[b]*HH + kc + j];
        }
        __syncthreads();
        for (int i = tid; i < 4096; i += 256) {
            int j = i >> 6, b = i & 63;
            g_embT[((size_t)t*HH + kc + j)*64 + b] = sm[j][b];
        }
        __syncthreads();
    }
    float4 z = make_float4(0.f,0.f,0.f,0.f);
    int gtid = blockIdx.x*256 + tid;                    // 65536 threads total
    for (int i = gtid; i < 2*SS*HB/4; i += 65536) {
        ((float4*)g_mh)[i] = z;
        ((float4*)g_mc)[i] = z;
    }
    for (int i = gtid; i < SS*HB/4; i += 65536)
        ((float4*)g_pm)[i] = z;
    if (gtid == 0) g_bar = 0u;
}

// ------------------------- parser conv1+bn+relu+conv2 partials -------------------------
__global__ void __launch_bounds__(256) k_parser(const float* __restrict__ w1,
        const float* __restrict__ c1b, const float* __restrict__ bng,
        const float* __restrict__ bnb, const float* __restrict__ w2)
{
    int chunk = blockIdx.x;
    int t     = blockIdx.y;
    int tx = threadIdx.x, ty = threadIdx.y;
    int tid = ty*64 + tx;
    int obase = chunk*16;
    __shared__ float e0s[4096], e1s[4096];
    __shared__ float2 ws[1024];
    __shared__ float red[4][64];
    float acc0=0.f, acc1=0.f, acc2=0.f, acc3=0.f;
    const float* s1 = &g_embT[(size_t)t*HB];
    const float* s0 = (t > 0) ? &g_embT[(size_t)(t-1)*HB] : 0;
    const float2* wv = (const float2*)w1;
    for (int kt = 0; kt < HH; kt += 64) {
        for (int i = tid; i < 4096; i += 256) {
            e1s[i] = s1[kt*64 + i];
            e0s[i] = s0 ? s0[kt*64 + i] : 0.f;
        }
        for (int i = tid; i < 1024; i += 256) {
            int o = i >> 6, k = i & 63;
            ws[i] = wv[(size_t)(obase+o)*HH + kt + k];
        }
        __syncthreads();
        #pragma unroll 8
        for (int k = 0; k < 64; k++) {
            float e0 = e0s[k*64 + tx];
            float e1 = e1s[k*64 + tx];
            float2 wa = ws[(ty*4+0)*64 + k];
            float2 wb = ws[(ty*4+1)*64 + k];
            float2 wc = ws[(ty*4+2)*64 + k];
            float2 wd = ws[(ty*4+3)*64 + k];
            acc0 += wa.x*e0 + wa.y*e1;
            acc1 += wb.x*e0 + wb.y*e1;
            acc2 += wc.x*e0 + wc.y*e1;
            acc3 += wd.x*e0 + wd.y*e1;
        }
        __syncthreads();
    }
    float part = 0.f;
    {
        int o0 = obase + ty*4;
        float v;
        v = bng[o0+0]*(acc0 + c1b[o0+0]) + bnb[o0+0]; part += w2[o0+0]*fmaxf(v, 0.f);
        v = bng[o0+1]*(acc1 + c1b[o0+1]) + bnb[o0+1]; part += w2[o0+1]*fmaxf(v, 0.f);
        v = bng[o0+2]*(acc2 + c1b[o0+2]) + bnb[o0+2]; part += w2[o0+2]*fmaxf(v, 0.f);
        v = bng[o0+3]*(acc3 + c1b[o0+3]) + bnb[o0+3]; part += w2[o0+3]*fmaxf(v, 0.f);
    }
    red[ty][tx] = part;
    __syncthreads();
    if (ty == 0)
        g_parts[((size_t)t*64 + chunk)*64 + tx] =
            red[0][tx] + red[1][tx] + red[2][tx] + red[3][tx];
}

// ------------------------- gates + masks (fused) -------------------------
__global__ void __launch_bounds__(256) k_gatemask(const float* __restrict__ c2b)
{
    int idx = blockIdx.x*256 + threadIdx.x;   // grid 64 -> (t,b)
    int t = idx >> 6, b = idx & 63;
    float c0 = c2b[0], c1 = c2b[1];
    float s1 = 0.f;
    for (int c = 32; c < 64; c++) s1 += g_parts[((size_t)t*64 + c)*64 + b];
    float gn = sigm(s1 + c1);
    float g0 = 0.f, cm = 1.f, cmn = 1.f;
    for (int s = 0; s < SS; s++) {
        float gh;
        if (t - s >= 0) {
            float s0 = 0.f;
            for (int c = 0; c < 32; c++) s0 += g_parts[((size_t)(t-s)*64 + c)*64 + b];
            gh = sigm(s0 + c0);
        } else gh = 1e8f;
        if (s == 0) g0 = gh;
        cm  *= sigm((g0 - gh)*100.f + 5.f);
        cmn *= sigm((gn - gh)*100.f + 5.f);
        g_mg [((size_t)t*SS + s)*64 + b] = cm;
        g_mgn[((size_t)t*SS + s)*64 + b] = cmn;
    }
}

// ------------------------- f32x2 GEMM tile (dup-weight smem, reg prefetch) ----------
__device__ __forceinline__ void gemm_tile(const float* __restrict__ W, int wstride,
    const float* __restrict__ X, float* __restrict__ part,
    int ob0, int k0, int klen, float* s_x, float* s_wd)
{
    int tid = threadIdx.x;
    int og = tid >> 4, bq = tid & 15;
    int r0 = tid >> 3, c0 = (tid & 7)*4;
    int r1 = (tid + 256) >> 3;
    unsigned long long a[4][2];
    #pragma unroll
    for (int o = 0; o < 4; o++) { a[o][0] = 0ull; a[o][1] = 0ull; }

    const float* Xp = X + (size_t)k0*64;
    float4 px0 = ldcg4(Xp + tid*4);
    float4 px1 = ldcg4(Xp + (tid + 256)*4);
    float4 pw0 = *(const float4*)&W[(size_t)(ob0+r0)*wstride + k0 + c0];   // L1-cached
    float4 pw1 = *(const float4*)&W[(size_t)(ob0+r1)*wstride + k0 + c0];

    for (int kt = 0; kt < klen; kt += 32) {
        ((float4*)s_x)[tid]       = px0;
        ((float4*)s_x)[tid + 256] = px1;
        {
            float* d0 = &s_wd[(r0*32 + c0)*2];
            *(float4*)d0       = make_float4(pw0.x, pw0.x, pw0.y, pw0.y);
            *(float4*)(d0 + 4) = make_float4(pw0.z, pw0.z, pw0.w, pw0.w);
            float* d1 = &s_wd[(r1*32 + c0)*2];
            *(float4*)d1       = make_float4(pw1.x, pw1.x, pw1.y, pw1.y);
            *(float4*)(d1 + 4) = make_float4(pw1.z, pw1.z, pw1.w, pw1.w);
        }
        __syncthreads();
        if (kt + 32 < klen) {               // prefetch next tile under compute
            const float* Xn = X + (size_t)(k0 + kt + 32)*64;
            px0 = ldcg4(Xn + tid*4);
            px1 = ldcg4(Xn + (tid + 256)*4);
            pw0 = *(const float4*)&W[(size_t)(ob0+r0)*wstride + k0 + kt + 32 + c0];
            pw1 = *(const float4*)&W[(size_t)(ob0+r1)*wstride + k0 + kt + 32 + c0];
        }
        #pragma unroll
        for (int kg = 0; kg < 8; kg++) {
            ulonglong2 xv0 = *(const ulonglong2*)&s_x[(kg*4+0)*64 + bq*4];
            ulonglong2 xv1 = *(const ulonglong2*)&s_x[(kg*4+1)*64 + bq*4];
            ulonglong2 xv2 = *(const ulonglong2*)&s_x[(kg*4+2)*64 + bq*4];
            ulonglong2 xv3 = *(const ulonglong2*)&s_x[(kg*4+3)*64 + bq*4];
            #pragma unroll
            for (int o = 0; o < 4; o++) {
                const float* wp = &s_wd[((og*4+o)*32 + kg*4)*2];
                ulonglong2 wa = *(const ulonglong2*)wp;
                ulonglong2 wc = *(const ulonglong2*)(wp + 4);
                FMA2(a[o][0], wa.x, xv0.x); FMA2(a[o][1], wa.x, xv0.y);
                FMA2(a[o][0], wa.y, xv1.x); FMA2(a[o][1], wa.y, xv1.y);
                FMA2(a[o][0], wc.x, xv2.x); FMA2(a[o][1], wc.x, xv2.y);
                FMA2(a[o][0], wc.y, xv3.x); FMA2(a[o][1], wc.y, xv3.y);
            }
        }
        __syncthreads();
    }
    #pragma unroll
    for (int o = 0; o < 4; o++) {
        float2 lo = *(float2*)&a[o][0];
        float2 hi = *(float2*)&a[o][1];
        stcg4(&part[(size_t)(ob0 + og*4 + o)*64 + bq*4], make_float4(lo.x, lo.y, hi.x, hi.y));
    }
}

// ------------------------- phase helpers -------------------------
__device__ __forceinline__ void combine16_all(const float* __restrict__ bias, int blk)
{
    int f = blk*256 + threadIdx.x;                  // float idx 0..65535
    float s = 0.f;
    #pragma unroll
    for (int p = 0; p < 16; p++)
        s += __ldcg(&g_partk[(size_t)p*65536 + f]);
    s += bias[f >> 6];
    __stcg(&g_key[f], s);
}

// 60 blocks: slot s (15), h-chunk c (4 x 256); partials into g_lp.
__device__ __forceinline__ void logits_block(const float* __restrict__ mem, int t,
                                             float* s_buf)
{
    int blk = blockIdx.x;
    int s = blk >> 2, c = blk & 3;
    int phys = (t + s) % SS;
    const float* m = mem + (size_t)phys*HB;
    int bq = threadIdx.x & 15, hg = threadIdx.x >> 4;
    float4 acc = make_float4(0,0,0,0);
    int h0 = c*256 + hg*16;
    #pragma unroll 4
    for (int h = h0; h < h0 + 16; h++) {
        float4 mv = ldcg4(m + h*64 + bq*4);
        float4 kv = ldcg4(g_key + h*64 + bq*4);
        acc.x += mv.x*kv.x; acc.y += mv.y*kv.y; acc.z += mv.z*kv.z; acc.w += mv.w*kv.w;
    }
    ((float4*)s_buf)[hg*16 + bq] = acc;
    __syncthreads();
    if (hg == 0) {
        float4 st = make_float4(0,0,0,0);
        #pragma unroll
        for (int g = 0; g < 16; g++) {
            float4 v = ((float4*)s_buf)[g*16 + bq];
            ADD4(st, v);
        }
        st.x *= 0.03125f; st.y *= 0.03125f; st.z *= 0.03125f; st.w *= 0.03125f;
        stcg4(&g_lp[(s*4 + c)*64 + bq*4], st);
    }
    __syncthreads();
}

__device__ __forceinline__ void softmax_att(const float* __restrict__ mask, float* att)
{
    int tid = threadIdx.x;
    if (tid < 64) {
        float lg[SS]; float mx = -1e30f;
        #pragma unroll
        for (int s = 0; s < SS; s++) {
            float v = __ldcg(&g_lp[(s*4+0)*64 + tid]) + __ldcg(&g_lp[(s*4+1)*64 + tid])
                    + __ldcg(&g_lp[(s*4+2)*64 + tid]) + __ldcg(&g_lp[(s*4+3)*64 + tid]);
            lg[s] = v; mx = fmaxf(mx, v);
        }
        float sum = 0.f;
        #pragma unroll
        for (int s = 0; s < SS; s++) {
            float e = expf(lg[s] - mx) * mask[s*64 + tid];
            att[s*64 + tid] = e; sum += e;
        }
        float inv = 1.f/(sum + 1e-8f);
        #pragma unroll
        for (int s = 0; s < SS; s++) att[s*64 + tid] *= inv;
    }
    __syncthreads();
}

// ALL 256 blocks: 4 h-rows per block.
__device__ __forceinline__ void select2_all(const float* __restrict__ memh,
        const float* __restrict__ memc, const float* __restrict__ mask, int t, int blk,
        float* att)
{
    softmax_att(mask, att);
    int b = threadIdx.x & 63, hi = threadIdx.x >> 6;
    int h = blk*4 + hi;
    float sh = 0.f, sc = 0.f;
    int p = t % SS;
    #pragma unroll
    for (int s = 0; s < SS; s++) {
        float a = att[s*64 + b];
        sh += a * __ldcg(&memh[(size_t)p*HB + h*64 + b]);
        sc += a * __ldcg(&memc[(size_t)p*HB + h*64 + b]);
        p++; if (p == SS) p = 0;
    }
    __stcg(&g_selh[h*64 + b], sh);
    __stcg(&g_selc[h*64 + b], sc);
}

// ALL 256 blocks: predictor select + pm ring update (exact-element ownership).
__device__ __forceinline__ void select1_all(const float* __restrict__ mask, int t, int blk,
                                            float* __restrict__ outsel, float* att)
{
    softmax_att(mask, att);
    int b = threadIdx.x & 63, hi = threadIdx.x >> 6;
    int h = blk*4 + hi;
    int p0 = t % SS;
    float sh = 0.f;
    int p = p0;
    #pragma unroll
    for (int s = 0; s < SS; s++) {
        sh += att[s*64 + b] * __ldcg(&g_pm[(size_t)p*HB + h*64 + b]);
        p++; if (p == SS) p = 0;
    }
    __stcg(&outsel[h*64 + b], sh);
    __stcg(&g_pm[(size_t)p0*HB + h*64 + b], __ldcg(&g_h2[h*64 + b]));
}

__device__ __forceinline__ void cell_block(const float* __restrict__ bih,
        const float* __restrict__ bhh, float* __restrict__ mh, float* __restrict__ mc,
        int slot, float* __restrict__ hout, float* __restrict__ hsout, int blk)
{
    int e4 = blk*256 + threadIdx.x;       // float4 idx 0..16383 (blocks 0..63)
    int h  = (e4*4) >> 6;
    int b4 = e4 & 15;
    float4 ig = make_float4(0,0,0,0), fg = ig, gg = ig, og = ig;
    #pragma unroll
    for (int p = 0; p < 4; p++) {
        const float* P = g_partg + (size_t)p*(4096*64);
        float4 v;
        v = ldcg4(P + ((       h)*16 + b4)*4); ADD4(ig, v);
        v = ldcg4(P + ((1024 + h)*16 + b4)*4); ADD4(fg, v);
        v = ldcg4(P + ((2048 + h)*16 + b4)*4); ADD4(gg, v);
        v = ldcg4(P + ((3072 + h)*16 + b4)*4); ADD4(og, v);
    }
    float bi = bih[h]        + bhh[h];
    float bf = bih[1024 + h] + bhh[1024 + h];
    float bg = bih[2048 + h] + bhh[2048 + h];
    float bo = bih[3072 + h] + bhh[3072 + h];
    float4 sc = ldcg4(&g_selc[e4*4]);
    float4 c4, h4;
    c4.x = sigm(fg.x + bf)*sc.x + sigm(ig.x + bi)*tanhf(gg.x + bg);
    c4.y = sigm(fg.y + bf)*sc.y + sigm(ig.y + bi)*tanhf(gg.y + bg);
    c4.z = sigm(fg.z + bf)*sc.z + sigm(ig.z + bi)*tanhf(gg.z + bg);
    c4.w = sigm(fg.w + bf)*sc.w + sigm(ig.w + bi)*tanhf(gg.w + bg);
    h4.x = sigm(og.x + bo)*tanhf(c4.x);
    h4.y = sigm(og.y + bo)*tanhf(c4.y);
    h4.z = sigm(og.z + bo)*tanhf(c4.z);
    h4.w = sigm(og.w + bo)*tanhf(c4.w);
    stcg4(mh + (size_t)slot*HB + e4*4, h4);
    stcg4(mc + (size_t)slot*HB + e4*4, c4);
    stcg4(hout + e4*4, h4);
    if (hsout) stcg4(hsout + e4*4, h4);
}

// ------------------------- persistent scan kernel (round-13 schedule) -------------------------
__global__ void __launch_bounds__(256, 2) k_scan(
    const float* __restrict__ wih, const float* __restrict__ whh,
    const float* __restrict__ bih, const float* __restrict__ bhh,
    const float* __restrict__ sw,  const float* __restrict__ sb,
    const float* __restrict__ pw,  const float* __restrict__ pb)
{
    __shared__ __align__(16) float s_x[2048];
    __shared__ __align__(16) float s_wd[4096];
    __shared__ float s_att[SS*64];
    int blk = blockIdx.x;
    unsigned ep = 0;

    #pragma unroll 1
    for (int t = 0; t < TT; t++) {
        int slot = t % SS, prev = (t + SS - 1) % SS;
        #pragma unroll 1
        for (int l = 0; l < 2; l++) {
            const float* x0  = l ? g_h1 : (g_embT + (size_t)t*HB);
            const float* mhl = g_mh + (size_t)l*SS*HB;
            const float* mcl = g_mc + (size_t)l*SS*HB;
            const float* Wsum = sw + (size_t)l*HH*2048;
            // -- key GEMM: 16 o-chunks x 16 k-slices
            {
                int ob0 = (blk >> 4)*64;
                int kg0 = (blk & 15)*128;
                const float* W; const float* X; int k0;
                if (kg0 >= 1024) { W = Wsum + 1024; X = mhl + (size_t)prev*HB; k0 = kg0 - 1024; }
                else             { W = Wsum;        X = x0;                    k0 = kg0; }
                gemm_tile(W, 2048, X, g_partk + (size_t)(blk & 15)*HB, ob0, k0, 128, s_x, s_wd);
            }
            gridbar(++ep);
            combine16_all(sb + l*HH, blk);
            gridbar(++ep);
            if (blk < 60) logits_block(mhl, t, s_x);
            gridbar(++ep);
            select2_all(mhl, mcl, g_mg + (size_t)t*SS*64, t, blk, s_att);
            gridbar(++ep);
            // -- gates GEMM: 64 o-chunks x 4 k-slices
            {
                int ob0 = (blk >> 2)*64;
                int kg0 = (blk & 3)*512;
                const float* W; const float* X; int k0;
                if (kg0 >= 1024) { W = whh + (size_t)l*4096*1024; X = g_selh; k0 = kg0 - 1024; }
                else             { W = wih + (size_t)l*4096*1024; X = x0;     k0 = kg0; }
                gemm_tile(W, 1024, X, g_partg + (size_t)(blk & 3)*(4096*64), ob0, k0, 512, s_x, s_wd);
            }
            gridbar(++ep);
            if (blk < 64) cell_block(bih + l*4096, bhh + l*4096,
                                     g_mh + (size_t)l*SS*HB, g_mc + (size_t)l*SS*HB, slot,
                                     l ? g_h2 : g_h1,
                                     l ? (g_hs + (size_t)t*HB) : (float*)0, blk);
            gridbar(++ep);
        }
        // -- predictor
        {
            int ob0 = (blk >> 4)*64;
            int kg0 = (blk & 15)*128;
            const float* W; const float* X; int k0;
            if (kg0 >= 1024) { W = pw + 1024; X = g_pm + (size_t)prev*HB; k0 = kg0 - 1024; }
            else             { W = pw;        X = g_h2;                   k0 = kg0; }
            gemm_tile(W, 2048, X, g_partk + (size_t)(blk & 15)*HB, ob0, k0, 128, s_x, s_wd);
        }
        gridbar(++ep);
        combine16_all(pb, blk);
        gridbar(++ep);
        if (blk < 60) logits_block(g_pm, t, s_x);
        gridbar(++ep);
        select1_all(g_mgn + (size_t)t*SS*64, t, blk, g_sels + (size_t)t*HB, s_att);
        gridbar(++ep);
    }
}

// ------------------------- final FFD GEMM + tanh + transpose store -------------------------
__global__ void __launch_bounds__(256) k_ffd(const float* __restrict__ W,
        const float* __restrict__ fb, const float* __restrict__ gma,
        const float* __restrict__ bta, float* __restrict__ out)
{
    __shared__ __align__(16) float xs[2048];
    __shared__ __align__(16) float ws[2048];
    __shared__ __align__(16) float tile[4096];
    int ob0 = blockIdx.x*64;
    int t   = blockIdx.y;
    int tid = threadIdx.x;
    int og = tid >> 4, bq = tid & 15;
    const float* xh = &g_hs  [(size_t)t*HB];
    const float* x2 = &g_sels[(size_t)t*HB];
    float4 a0 = make_float4(0,0,0,0), a1 = a0, a2 = a0, a3 = a0;
    for (int kt = 0; kt < 2048; kt += 32) {
        const float* X = (kt < 1024) ? xh + kt*64 : x2 + (kt - 1024)*64;
        const float4* Xt = (const float4*)X;
        ((float4*)xs)[tid]       = Xt[tid];
        ((float4*)xs)[tid + 256] = Xt[tid + 256];
        #pragma unroll
        for (int r = 0; r < 2; r++) {
            int li = tid + r*256;
            int row = li >> 3, c4 = li & 7;
            ((float4*)ws)[li] = *(const float4*)&W[(size_t)(ob0+row)*2048 + kt + c4*4];
        }
        __syncthreads();
        #pragma unroll
        for (int kg = 0; kg < 8; kg++) {
            float4 xv0 = *(float4*)&xs[(kg*4+0)*64 + bq*4];
            float4 xv1 = *(float4*)&xs[(kg*4+1)*64 + bq*4];
            float4 xv2 = *(float4*)&xs[(kg*4+2)*64 + bq*4];
            float4 xv3 = *(float4*)&xs[(kg*4+3)*64 + bq*4];
            float4 wv0 = *(float4*)&ws[(og*4+0)*32 + kg*4];
            float4 wv1 = *(float4*)&ws[(og*4+1)*32 + kg*4];
            float4 wv2 = *(float4*)&ws[(og*4+2)*32 + kg*4];
            float4 wv3 = *(float4*)&ws[(og*4+3)*32 + kg*4];
            FMA4(a0, wv0.x, xv0) FMA4(a0, wv0.y, xv1) FMA4(a0, wv0.z, xv2) FMA4(a0, wv0.w, xv3)
            FMA4(a1, wv1.x, xv0) FMA4(a1, wv1.y, xv1) FMA4(a1, wv1.z, xv2) FMA4(a1, wv1.w, xv3)
            FMA4(a2, wv2.x, xv0) FMA4(a2, wv2.y, xv1) FMA4(a2, wv2.z, xv2) FMA4(a2, wv2.w, xv3)
            FMA4(a3, wv3.x, xv0) FMA4(a3, wv3.y, xv1) FMA4(a3, wv3.z, xv2) FMA4(a3, wv3.w, xv3)
        }
        __syncthreads();
    }
    float4 accs[4] = {a0, a1, a2, a3};
    #pragma unroll
    for (int i = 0; i < 4; i++) {
        int o = ob0 + og*4 + i;
        float g_ = gma[o], be = bta[o], bi = fb[o];
        float4 a = accs[i];
        a.x = tanhf(g_*(a.x + bi) + be);
        a.y = tanhf(g_*(a.y + bi) + be);
        a.z = tanhf(g_*(a.z + bi) + be);
        a.w = tanhf(g_*(a.w + bi) + be);
        *(float4*)&tile[(og*4+i)*64 + bq*4] = a;
    }
    __syncthreads();
    for (int r = 0; r < 16; r++) {
        int idx = r*256 + tid;
        int bb2 = idx >> 6, oo = idx & 63;
        out[((size_t)(t*64 + bb2))*HH + ob0 + oo] = tile[oo*64 + bb2];
    }
}

// ------------------------- mask tail of output -------------------------
__global__ void k_maskf(const int* __restrict__ tok, float* __restrict__ dst, int rem)
{
    for (int i = blockIdx.x*256 + threadIdx.x; i < rem; i += gridDim.x*256)
        dst[i] = (i < TT*BB) ? (tok[i] != 0 ? 1.f : 0.f) : 0.f;
}
__global__ void k_maskb(const int* __restrict__ tok, unsigned char* __restrict__ dst)
{
    int i = blockIdx.x*256 + threadIdx.x;
    if (i < TT*BB) dst[i] = (tok[i] != 0) ? 1 : 0;
}

// ------------------------- launch -------------------------
extern "C" void kernel_launch(void* const* d_in, const int* in_sizes, int n_in,
                              void* d_out, int out_size)
{
    const int*   tokens = (const int*)  d_in[0];
    const float* embt   = (const float*)d_in[1];
    const float* c1w = (const float*)d_in[2];
    const float* c1b = (const float*)d_in[3];
    const float* bng = (const float*)d_in[4];
    const float* bnb = (const float*)d_in[5];
    const float* c2w = (const float*)d_in[6];
    const float* c2b = (const float*)d_in[7];
    const float* wih = (const float*)d_in[8];
    const float* whh = (const float*)d_in[9];
    const float* bih = (const float*)d_in[10];
    const float* bhh = (const float*)d_in[11];
    const float* sw  = (const float*)d_in[12];
    const float* sb  = (const float*)d_in[13];
    const float* pw  = (const float*)d_in[14];
    const float* pb  = (const float*)d_in[15];
    const float* fw  = (const float*)d_in[16];
    const float* fb  = (const float*)d_in[17];
    const float* fg  = (const float*)d_in[18];
    const float* fbe = (const float*)d_in[19];
    float* out = (float*)d_out;

    k_embzero<<<TT, 256>>>(tokens, embt);
    k_parser<<<dim3(64, TT), dim3(64, 4)>>>(c1w, c1b, bng, bnb, c2w);
    k_gatemask<<<64, 256>>>(c2b);

    // single persistent node for the whole 256-step recurrence
    k_scan<<<NB, 256>>>(wih, whh, bih, bhh, sw, sb, pw, pb);

    k_ffd<<<dim3(16, TT), 256>>>(fw, fb, fg, fbe, out);

    int rem = out_size - TT*BB*HH;
    if (rem > 0) {
        if (rem == TT*BB/4)
            k_maskb<<<64, 256>>>(tokens, (unsigned char*)out + (size_t)TT*BB*HH*4);
        else
            k_maskf<<<64, 256>>>(tokens, out + (size_t)TT*BB*HH, rem);
    }
}

// round 16
// speedup vs baseline: 1.2963x; 1.1734x over previous
#include <cuda_runtime.h>
#include <math.h>

#define TT 256
#define BB 64
#define HH 1024
#define SS 15
#define HB (HH*BB)          // 65536 floats per (H,B) plane
#define NB 256              // persistent grid (2 CTAs/SM x 148 SMs >= 256)

// ------------------------- static device scratch -------------------------
__device__ __align__(16) float g_embT [(size_t)TT*HB];      // (t, h, b)
__device__ __align__(16) float g_parts[(size_t)TT*64*BB];   // parser partials
__device__ __align__(16) float g_mg  [TT*SS*BB];            // (t, s, b)
__device__ __align__(16) float g_mgn [TT*SS*BB];
__device__ __align__(16) float g_mh  [2*SS*HB];             // rings (layer, slot, h, b)
__device__ __align__(16) float g_mc  [2*SS*HB];
__device__ __align__(16) float g_pm  [SS*HB];
__device__ __align__(16) float g_h1  [HB];
__device__ __align__(16) float g_h2  [HB];
__device__ __align__(16) float g_key [HB];
__device__ __align__(16) float g_lp  [60*64];               // logits partials (s*4+c, b)
__device__ __align__(16) float g_selh[HB];
__device__ __align__(16) float g_selc[HB];
__device__ __align__(16) float g_partk[32*HB];              // key GEMM partials (ksplit=32)
__device__ __align__(16) float g_partg[8*4096*64];          // gates GEMM partials (ksplit=8)
__device__ __align__(16) float g_hs  [(size_t)TT*HB];
__device__ __align__(16) float g_sels[(size_t)TT*HB];

__device__ unsigned g_bar;     // global barrier counter

__device__ __forceinline__ float sigm(float x){ return 1.f/(1.f+expf(-x)); }

#define ADD4(a, v) { (a).x += (v).x; (a).y += (v).y; (a).z += (v).z; (a).w += (v).w; }
#define FMA4(a, s, v) { (a).x += (s)*(v).x; (a).y += (s)*(v).y; (a).z += (s)*(v).z; (a).w += (s)*(v).w; }
// packed fp32x2 FMA (SASS FFMA2): IEEE fp32 per lane
#define FMA2(acc, w, x) asm("fma.rn.f32x2 %0, %1, %2, %0;" : "+l"(acc) : "l"(w), "l"(x))
#define DUP2(p, f)      asm("mov.b64 %0, {%1, %1};" : "=l"(p) : "r"(__float_as_uint(f)))

__device__ __forceinline__ float4 ldcg4(const float* p){ return __ldcg((const float4*)p); }
__device__ __forceinline__ void   stcg4(float* p, float4 v){ __stcg((float4*)p, v); }

// ------------------------- grid barrier (fence-free, .cg data discipline) ---------
__device__ __forceinline__ void gridbar(unsigned ep)
{
    __syncthreads();
    if (threadIdx.x == 0) {
        asm volatile("red.release.gpu.global.add.u32 [%0], 1;" :: "l"(&g_bar) : "memory");
        unsigned tgt = ep * NB, v;
        asm volatile("ld.acquire.gpu.global.u32 %0, [%1];" : "=r"(v) : "l"(&g_bar) : "memory");
        while (v < tgt) {
            __nanosleep(64);
            asm volatile("ld.acquire.gpu.global.u32 %0, [%1];" : "=r"(v) : "l"(&g_bar) : "memory");
        }
    }
    __syncthreads();
}

// ------------------------- embedding gather + transpose + ring zero ------------
__global__ void __launch_bounds__(256) k_embzero(const int* __restrict__ tok,
                                                 const float* __restrict__ table)
{
    int t = blockIdx.x, tid = threadIdx.x;
    __shared__ float sm[64][65];
    __shared__ int stok[64];
    if (tid < 64) stok[tid] = tok[t*64 + tid];
    __syncthreads();
    for (int kc = 0; kc < HH; kc += 64) {
        for (int i = tid; i < 4096; i += 256) {
            int b = i >> 6, j = i & 63;
            sm[j][b] = table[(size_t)stok[b]*HH + kc + j];
        }
        __syncthreads();
        for (int i = tid; i < 4096; i += 256) {
            int j = i >> 6, b = i & 63;
            g_embT[((size_t)t*HH + kc + j)*64 + b] = sm[j][b];
        }
        __syncthreads();
    }
    float4 z = make_float4(0.f,0.f,0.f,0.f);
    int gtid = blockIdx.x*256 + tid;                    // 65536 threads total
    for (int i = gtid; i < 2*SS*HB/4; i += 65536) {
        ((float4*)g_mh)[i] = z;
        ((float4*)g_mc)[i] = z;
    }
    for (int i = gtid; i < SS*HB/4; i += 65536)
        ((float4*)g_pm)[i] = z;
    if (gtid == 0) g_bar = 0u;
}

// ------------------------- parser conv1+bn+relu+conv2 partials -------------------------
__global__ void __launch_bounds__(256) k_parser(const float* __restrict__ w1,
        const float* __restrict__ c1b, const float* __restrict__ bng,
        const float* __restrict__ bnb, const float* __restrict__ w2)
{
    int chunk = blockIdx.x;
    int t     = blockIdx.y;
    int tx = threadIdx.x, ty = threadIdx.y;
    int tid = ty*64 + tx;
    int obase = chunk*16;
    __shared__ float e0s[4096], e1s[4096];
    __shared__ float2 ws[1024];
    __shared__ float red[4][64];
    float acc0=0.f, acc1=0.f, acc2=0.f, acc3=0.f;
    const float* s1 = &g_embT[(size_t)t*HB];
    const float* s0 = (t > 0) ? &g_embT[(size_t)(t-1)*HB] : 0;
    const float2* wv = (const float2*)w1;
    for (int kt = 0; kt < HH; kt += 64) {
        for (int i = tid; i < 4096; i += 256) {
            e1s[i] = s1[kt*64 + i];
            e0s[i] = s0 ? s0[kt*64 + i] : 0.f;
        }
        for (int i = tid; i < 1024; i += 256) {
            int o = i >> 6, k = i & 63;
            ws[i] = wv[(size_t)(obase+o)*HH + kt + k];
        }
        __syncthreads();
        #pragma unroll 8
        for (int k = 0; k < 64; k++) {
            float e0 = e0s[k*64 + tx];
            float e1 = e1s[k*64 + tx];
            float2 wa = ws[(ty*4+0)*64 + k];
            float2 wb = ws[(ty*4+1)*64 + k];
            float2 wc = ws[(ty*4+2)*64 + k];
            float2 wd = ws[(ty*4+3)*64 + k];
            acc0 += wa.x*e0 + wa.y*e1;
            acc1 += wb.x*e0 + wb.y*e1;
            acc2 += wc.x*e0 + wc.y*e1;
            acc3 += wd.x*e0 + wd.y*e1;
        }
        __syncthreads();
    }
    float part = 0.f;
    {
        int o0 = obase + ty*4;
        float v;
        v = bng[o0+0]*(acc0 + c1b[o0+0]) + bnb[o0+0]; part += w2[o0+0]*fmaxf(v, 0.f);
        v = bng[o0+1]*(acc1 + c1b[o0+1]) + bnb[o0+1]; part += w2[o0+1]*fmaxf(v, 0.f);
        v = bng[o0+2]*(acc2 + c1b[o0+2]) + bnb[o0+2]; part += w2[o0+2]*fmaxf(v, 0.f);
        v = bng[o0+3]*(acc3 + c1b[o0+3]) + bnb[o0+3]; part += w2[o0+3]*fmaxf(v, 0.f);
    }
    red[ty][tx] = part;
    __syncthreads();
    if (ty == 0)
        g_parts[((size_t)t*64 + chunk)*64 + tx] =
            red[0][tx] + red[1][tx] + red[2][tx] + red[3][tx];
}

// ------------------------- gates + masks (fused) -------------------------
__global__ void __launch_bounds__(256) k_gatemask(const float* __restrict__ c2b)
{
    int idx = blockIdx.x*256 + threadIdx.x;   // grid 64 -> (t,b)
    int t = idx >> 6, b = idx & 63;
    float c0 = c2b[0], c1 = c2b[1];
    float s1 = 0.f;
    for (int c = 32; c < 64; c++) s1 += g_parts[((size_t)t*64 + c)*64 + b];
    float gn = sigm(s1 + c1);
    float g0 = 0.f, cm = 1.f, cmn = 1.f;
    for (int s = 0; s < SS; s++) {
        float gh;
        if (t - s >= 0) {
            float s0 = 0.f;
            for (int c = 0; c < 32; c++) s0 += g_parts[((size_t)(t-s)*64 + c)*64 + b];
            gh = sigm(s0 + c0);
        } else gh = 1e8f;
        if (s == 0) g0 = gh;
        cm  *= sigm((g0 - gh)*100.f + 5.f);
        cmn *= sigm((gn - gh)*100.f + 5.f);
        g_mg [((size_t)t*SS + s)*64 + b] = cm;
        g_mgn[((size_t)t*SS + s)*64 + b] = cmn;
    }
}

// ------------------------- FMA2 GEMM tile: 128-row o-tile, 8o x 4b per thread ----------
// s_x: 2048 floats ([32 k][64 b]); s_w: 4096 floats ([128 row][32 k]).
__device__ __forceinline__ void gemm_tile2(const float* __restrict__ W, int wstride,
    const float* __restrict__ X, float* __restrict__ part,
    int ob0, int k0, int klen, float* s_x, float* s_w)
{
    int tid = threadIdx.x;
    int og = tid >> 4, bq = tid & 15;       // og: 16 groups x 8 rows; bq: 16 x 4 b
    unsigned long long acc[8][2];
    #pragma unroll
    for (int o = 0; o < 8; o++) { acc[o][0] = 0ull; acc[o][1] = 0ull; }

    const float* Xp = X + (size_t)k0*64;
    float4 px0 = ldcg4(Xp + tid*4);
    float4 px1 = ldcg4(Xp + (tid + 256)*4);
    float4 pw[4];
    #pragma unroll
    for (int j = 0; j < 4; j++) {
        int idx = j*256 + tid;
        int row = idx >> 3, kc = (idx & 7)*4;
        pw[j] = *(const float4*)&W[(size_t)(ob0+row)*wstride + k0 + kc];
    }

    for (int kt = 0; kt < klen; kt += 32) {
        ((float4*)s_x)[tid]       = px0;
        ((float4*)s_x)[tid + 256] = px1;
        #pragma unroll
        for (int j = 0; j < 4; j++)
            ((float4*)s_w)[j*256 + tid] = pw[j];     // f4 idx == row*8 + kc/4
        __syncthreads();
        if (kt + 32 < klen) {                        // prefetch next tile under compute
            const float* Xn = X + (size_t)(k0 + kt + 32)*64;
            px0 = ldcg4(Xn + tid*4);
            px1 = ldcg4(Xn + (tid + 256)*4);
            #pragma unroll
            for (int j = 0; j < 4; j++) {
                int idx = j*256 + tid;
                int row = idx >> 3, kc = (idx & 7)*4;
                pw[j] = *(const float4*)&W[(size_t)(ob0+row)*wstride + k0 + kt + 32 + kc];
            }
        }
        #pragma unroll
        for (int kg = 0; kg < 8; kg++) {
            ulonglong2 xq0 = *(const ulonglong2*)&s_x[(kg*4+0)*64 + bq*4];
            ulonglong2 xq1 = *(const ulonglong2*)&s_x[(kg*4+1)*64 + bq*4];
            ulonglong2 xq2 = *(const ulonglong2*)&s_x[(kg*4+2)*64 + bq*4];
            ulonglong2 xq3 = *(const ulonglong2*)&s_x[(kg*4+3)*64 + bq*4];
            #pragma unroll
            for (int o = 0; o < 8; o++) {
                float4 wv = *(const float4*)&s_w[(og*8+o)*32 + kg*4];
                unsigned long long p0, p1, p2, p3;
                DUP2(p0, wv.x); DUP2(p1, wv.y); DUP2(p2, wv.z); DUP2(p3, wv.w);
                FMA2(acc[o][0], p0, xq0.x); FMA2(acc[o][1], p0, xq0.y);
                FMA2(acc[o][0], p1, xq1.x); FMA2(acc[o][1], p1, xq1.y);
                FMA2(acc[o][0], p2, xq2.x); FMA2(acc[o][1], p2, xq2.y);
                FMA2(acc[o][0], p3, xq3.x); FMA2(acc[o][1], p3, xq3.y);
            }
        }
        __syncthreads();
    }
    #pragma unroll
    for (int o = 0; o < 8; o++) {
        float2 lo = *(float2*)&acc[o][0];
        float2 hi = *(float2*)&acc[o][1];
        stcg4(&part[(size_t)(ob0 + og*8 + o)*64 + bq*4], make_float4(lo.x, lo.y, hi.x, hi.y));
    }
}

// ------------------------- phase helpers -------------------------
__device__ __forceinline__ void combine32_all(const float* __restrict__ bias, int blk)
{
    int f = blk*256 + threadIdx.x;                  // float idx 0..65535
    float s = 0.f;
    #pragma unroll
    for (int p = 0; p < 32; p++)
        s += __ldcg(&g_partk[(size_t)p*65536 + f]);
    s += bias[f >> 6];
    __stcg(&g_key[f], s);
}

// 60 blocks: slot s (15), h-chunk c (4 x 256); partials into g_lp.
__device__ __forceinline__ void logits_block(const float* __restrict__ mem, int t,
                                             float* s_buf)
{
    int blk = blockIdx.x;
    int s = blk >> 2, c = blk & 3;
    int phys = (t + s) % SS;
    const float* m = mem + (size_t)phys*HB;
    int bq = threadIdx.x & 15, hg = threadIdx.x >> 4;
    float4 acc = make_float4(0,0,0,0);
    int h0 = c*256 + hg*16;
    #pragma unroll 4
    for (int h = h0; h < h0 + 16; h++) {
        float4 mv = ldcg4(m + h*64 + bq*4);
        float4 kv = ldcg4(g_key + h*64 + bq*4);
        acc.x += mv.x*kv.x; acc.y += mv.y*kv.y; acc.z += mv.z*kv.z; acc.w += mv.w*kv.w;
    }
    ((float4*)s_buf)[hg*16 + bq] = acc;
    __syncthreads();
    if (hg == 0) {
        float4 st = make_float4(0,0,0,0);
        #pragma unroll
        for (int g = 0; g < 16; g++) {
            float4 v = ((float4*)s_buf)[g*16 + bq];
            ADD4(st, v);
        }
        st.x *= 0.03125f; st.y *= 0.03125f; st.z *= 0.03125f; st.w *= 0.03125f;
        stcg4(&g_lp[(s*4 + c)*64 + bq*4], st);
    }
    __syncthreads();
}

__device__ __forceinline__ void softmax_att(const float* __restrict__ mask, float* att)
{
    int tid = threadIdx.x;
    if (tid < 64) {
        float lg[SS]; float mx = -1e30f;
        #pragma unroll
        for (int s = 0; s < SS; s++) {
            float v = __ldcg(&g_lp[(s*4+0)*64 + tid]) + __ldcg(&g_lp[(s*4+1)*64 + tid])
                    + __ldcg(&g_lp[(s*4+2)*64 + tid]) + __ldcg(&g_lp[(s*4+3)*64 + tid]);
            lg[s] = v; mx = fmaxf(mx, v);
        }
        float sum = 0.f;
        #pragma unroll
        for (int s = 0; s < SS; s++) {
            float e = expf(lg[s] - mx) * mask[s*64 + tid];
            att[s*64 + tid] = e; sum += e;
        }
        float inv = 1.f/(sum + 1e-8f);
        #pragma unroll
        for (int s = 0; s < SS; s++) att[s*64 + tid] *= inv;
    }
    __syncthreads();
}

// ALL 256 blocks: 4 h-rows per block.
__device__ __forceinline__ void select2_all(const float* __restrict__ memh,
        const float* __restrict__ memc, const float* __restrict__ mask, int t, int blk,
        float* att)
{
    softmax_att(mask, att);
    int b = threadIdx.x & 63, hi = threadIdx.x >> 6;
    int h = blk*4 + hi;
    float sh = 0.f, sc = 0.f;
    int p = t % SS;
    #pragma unroll
    for (int s = 0; s < SS; s++) {
        float a = att[s*64 + b];
        sh += a * __ldcg(&memh[(size_t)p*HB + h*64 + b]);
        sc += a * __ldcg(&memc[(size_t)p*HB + h*64 + b]);
        p++; if (p == SS) p = 0;
    }
    __stcg(&g_selh[h*64 + b], sh);
    __stcg(&g_selc[h*64 + b], sc);
}

// ALL 256 blocks: predictor select + pm ring update (exact-element ownership).
__device__ __forceinline__ void select1_all(const float* __restrict__ mask, int t, int blk,
                                            float* __restrict__ outsel, float* att)
{
    softmax_att(mask, att);
    int b = threadIdx.x & 63, hi = threadIdx.x >> 6;
    int h = blk*4 + hi;
    int p0 = t % SS;
    float sh = 0.f;
    int p = p0;
    #pragma unroll
    for (int s = 0; s < SS; s++) {
        sh += att[s*64 + b] * __ldcg(&g_pm[(size_t)p*HB + h*64 + b]);
        p++; if (p == SS) p = 0;
    }
    __stcg(&outsel[h*64 + b], sh);
    __stcg(&g_pm[(size_t)p0*HB + h*64 + b], __ldcg(&g_h2[h*64 + b]));
}

__device__ __forceinline__ void cell_block(const float* __restrict__ bih,
        const float* __restrict__ bhh, float* __restrict__ mh, float* __restrict__ mc,
        int slot, float* __restrict__ hout, float* __restrict__ hsout, int blk)
{
    int e4 = blk*256 + threadIdx.x;       // float4 idx 0..16383 (blocks 0..63)
    int h  = (e4*4) >> 6;
    int b4 = e4 & 15;
    float4 ig = make_float4(0,0,0,0), fg = ig, gg = ig, og = ig;
    #pragma unroll
    for (int p = 0; p < 8; p++) {
        const float* P = g_partg + (size_t)p*(4096*64);
        float4 v;
        v = ldcg4(P + ((       h)*16 + b4)*4); ADD4(ig, v);
        v = ldcg4(P + ((1024 + h)*16 + b4)*4); ADD4(fg, v);
        v = ldcg4(P + ((2048 + h)*16 + b4)*4); ADD4(gg, v);
        v = ldcg4(P + ((3072 + h)*16 + b4)*4); ADD4(og, v);
    }
    float bi = bih[h]        + bhh[h];
    float bf = bih[1024 + h] + bhh[1024 + h];
    float bg = bih[2048 + h] + bhh[2048 + h];
    float bo = bih[3072 + h] + bhh[3072 + h];
    float4 sc = ldcg4(&g_selc[e4*4]);
    float4 c4, h4;
    c4.x = sigm(fg.x + bf)*sc.x + sigm(ig.x + bi)*tanhf(gg.x + bg);
    c4.y = sigm(fg.y + bf)*sc.y + sigm(ig.y + bi)*tanhf(gg.y + bg);
    c4.z = sigm(fg.z + bf)*sc.z + sigm(ig.z + bi)*tanhf(gg.z + bg);
    c4.w = sigm(fg.w + bf)*sc.w + sigm(ig.w + bi)*tanhf(gg.w + bg);
    h4.x = sigm(og.x + bo)*tanhf(c4.x);
    h4.y = sigm(og.y + bo)*tanhf(c4.y);
    h4.z = sigm(og.z + bo)*tanhf(c4.z);
    h4.w = sigm(og.w + bo)*tanhf(c4.w);
    stcg4(mh + (size_t)slot*HB + e4*4, h4);
    stcg4(mc + (size_t)slot*HB + e4*4, c4);
    stcg4(hout + e4*4, h4);
    if (hsout) stcg4(hsout + e4*4, h4);
}

// ------------------------- persistent scan kernel (R13 schedule, FMA2 tiles) ----------
__global__ void __launch_bounds__(256, 2) k_scan(
    const float* __restrict__ wih, const float* __restrict__ whh,
    const float* __restrict__ bih, const float* __restrict__ bhh,
    const float* __restrict__ sw,  const float* __restrict__ sb,
    const float* __restrict__ pw,  const float* __restrict__ pb)
{
    __shared__ __align__(16) float s_x[2048];
    __shared__ __align__(16) float s_w[4096];
    __shared__ float s_att[SS*64];
    int blk = blockIdx.x;
    unsigned ep = 0;

    #pragma unroll 1
    for (int t = 0; t < TT; t++) {
        int slot = t % SS, prev = (t + SS - 1) % SS;
        #pragma unroll 1
        for (int l = 0; l < 2; l++) {
            const float* x0  = l ? g_h1 : (g_embT + (size_t)t*HB);
            const float* mhl = g_mh + (size_t)l*SS*HB;
            const float* mcl = g_mc + (size_t)l*SS*HB;
            const float* Wsum = sw + (size_t)l*HH*2048;
            // -- key GEMM: 8 o-tiles(128) x 32 k-slices (K=64)
            {
                int ob0 = (blk >> 5)*128;
                int ks  = blk & 31;
                int kg0 = ks*64;
                const float* W; const float* X; int k0;
                if (kg0 >= 1024) { W = Wsum + 1024; X = mhl + (size_t)prev*HB; k0 = kg0 - 1024; }
                else             { W = Wsum;        X = x0;                    k0 = kg0; }
                gemm_tile2(W, 2048, X, g_partk + (size_t)ks*HB, ob0, k0, 64, s_x, s_w);
            }
            gridbar(++ep);
            combine32_all(sb + l*HH, blk);
            gridbar(++ep);
            if (blk < 60) logits_block(mhl, t, s_x);
            gridbar(++ep);
            select2_all(mhl, mcl, g_mg + (size_t)t*SS*64, t, blk, s_att);
            gridbar(++ep);
            // -- gates GEMM: 32 o-tiles(128) x 8 k-slices (K=256)
            {
                int ob0 = (blk >> 3)*128;
                int ks  = blk & 7;
                int kg0 = ks*256;
                const float* W; const float* X; int k0;
                if (kg0 >= 1024) { W = whh + (size_t)l*4096*1024; X = g_selh; k0 = kg0 - 1024; }
                else             { W = wih + (size_t)l*4096*1024; X = x0;     k0 = kg0; }
                gemm_tile2(W, 1024, X, g_partg + (size_t)ks*(4096*64), ob0, k0, 256, s_x, s_w);
            }
            gridbar(++ep);
            if (blk < 64) cell_block(bih + l*4096, bhh + l*4096,
                                     g_mh + (size_t)l*SS*HB, g_mc + (size_t)l*SS*HB, slot,
                                     l ? g_h2 : g_h1,
                                     l ? (g_hs + (size_t)t*HB) : (float*)0, blk);
            gridbar(++ep);
        }
        // -- predictor key GEMM
        {
            int ob0 = (blk >> 5)*128;
            int ks  = blk & 31;
            int kg0 = ks*64;
            const float* W; const float* X; int k0;
            if (kg0 >= 1024) { W = pw + 1024; X = g_pm + (size_t)prev*HB; k0 = kg0 - 1024; }
            else             { W = pw;        X = g_h2;                   k0 = kg0; }
            gemm_tile2(W, 2048, X, g_partk + (size_t)ks*HB, ob0, k0, 64, s_x, s_w);
        }
        gridbar(++ep);
        combine32_all(pb, blk);
        gridbar(++ep);
        if (blk < 60) logits_block(g_pm, t, s_x);
        gridbar(++ep);
        select1_all(g_mgn + (size_t)t*SS*64, t, blk, g_sels + (size_t)t*HB, s_att);
        gridbar(++ep);
    }
}

// ------------------------- final FFD GEMM + tanh + transpose store -------------------------
__global__ void __launch_bounds__(256) k_ffd(const float* __restrict__ W,
        const float* __restrict__ fb, const float* __restrict__ gma,
        const float* __restrict__ bta, float* __restrict__ out)
{
    __shared__ __align__(16) float xs[2048];
    __shared__ __align__(16) float ws[2048];
    __shared__ __align__(16) float tile[4096];
    int ob0 = blockIdx.x*64;
    int t   = blockIdx.y;
    int tid = threadIdx.x;
    int og = tid >> 4, bq = tid & 15;
    const float* xh = &g_hs  [(size_t)t*HB];
    const float* x2 = &g_sels[(size_t)t*HB];
    float4 a0 = make_float4(0,0,0,0), a1 = a0, a2 = a0, a3 = a0;
    for (int kt = 0; kt < 2048; kt += 32) {
        const float* X = (kt < 1024) ? xh + kt*64 : x2 + (kt - 1024)*64;
        const float4* Xt = (const float4*)X;
        ((float4*)xs)[tid]       = Xt[tid];
        ((float4*)xs)[tid + 256] = Xt[tid + 256];
        #pragma unroll
        for (int r = 0; r < 2; r++) {
            int li = tid + r*256;
            int row = li >> 3, c4 = li & 7;
            ((float4*)ws)[li] = *(const float4*)&W[(size_t)(ob0+row)*2048 + kt + c4*4];
        }
        __syncthreads();
        #pragma unroll
        for (int kg = 0; kg < 8; kg++) {
            float4 xv0 = *(float4*)&xs[(kg*4+0)*64 + bq*4];
            float4 xv1 = *(float4*)&xs[(kg*4+1)*64 + bq*4];
            float4 xv2 = *(float4*)&xs[(kg*4+2)*64 + bq*4];
            float4 xv3 = *(float4*)&xs[(kg*4+3)*64 + bq*4];
            float4 wv0 = *(float4*)&ws[(og*4+0)*32 + kg*4];
            float4 wv1 = *(float4*)&ws[(og*4+1)*32 + kg*4];
            float4 wv2 = *(float4*)&ws[(og*4+2)*32 + kg*4];
            float4 wv3 = *(float4*)&ws[(og*4+3)*32 + kg*4];
            FMA4(a0, wv0.x, xv0) FMA4(a0, wv0.y, xv1) FMA4(a0, wv0.z, xv2) FMA4(a0, wv0.w, xv3)
            FMA4(a1, wv1.x, xv0) FMA4(a1, wv1.y, xv1) FMA4(a1, wv1.z, xv2) FMA4(a1, wv1.w, xv3)
            FMA4(a2, wv2.x, xv0) FMA4(a2, wv2.y, xv1) FMA4(a2, wv2.z, xv2) FMA4(a2, wv2.w, xv3)
            FMA4(a3, wv3.x, xv0) FMA4(a3, wv3.y, xv1) FMA4(a3, wv3.z, xv2) FMA4(a3, wv3.w, xv3)
        }
        __syncthreads();
    }
    float4 accs[4] = {a0, a1, a2, a3};
    #pragma unroll
    for (int i = 0; i < 4; i++) {
        int o = ob0 + og*4 + i;
        float g_ = gma[o], be = bta[o], bi = fb[o];
        float4 a = accs[i];
        a.x = tanhf(g_*(a.x + bi) + be);
        a.y = tanhf(g_*(a.y + bi) + be);
        a.z = tanhf(g_*(a.z + bi) + be);
        a.w = tanhf(g_*(a.w + bi) + be);
        *(float4*)&tile[(og*4+i)*64 + bq*4] = a;
    }
    __syncthreads();
    for (int r = 0; r < 16; r++) {
        int idx = r*256 + tid;
        int bb2 = idx >> 6, oo = idx & 63;
        out[((size_t)(t*64 + bb2))*HH + ob0 + oo] = tile[oo*64 + bb2];
    }
}

// ------------------------- mask tail of output -------------------------
__global__ void k_maskf(const int* __restrict__ tok, float* __restrict__ dst, int rem)
{
    for (int i = blockIdx.x*256 + threadIdx.x; i < rem; i += gridDim.x*256)
        dst[i] = (i < TT*BB) ? (tok[i] != 0 ? 1.f : 0.f) : 0.f;
}
__global__ void k_maskb(const int* __restrict__ tok, unsigned char* __restrict__ dst)
{
    int i = blockIdx.x*256 + threadIdx.x;
    if (i < TT*BB) dst[i] = (tok[i] != 0) ? 1 : 0;
}

// ------------------------- launch -------------------------
extern "C" void kernel_launch(void* const* d_in, const int* in_sizes, int n_in,
                              void* d_out, int out_size)
{
    const int*   tokens = (const int*)  d_in[0];
    const float* embt   = (const float*)d_in[1];
    const float* c1w = (const float*)d_in[2];
    const float* c1b = (const float*)d_in[3];
    const float* bng = (const float*)d_in[4];
    const float* bnb = (const float*)d_in[5];
    const float* c2w = (const float*)d_in[6];
    const float* c2b = (const float*)d_in[7];
    const float* wih = (const float*)d_in[8];
    const float* whh = (const float*)d_in[9];
    const float* bih = (const float*)d_in[10];
    const float* bhh = (const float*)d_in[11];
    const float* sw  = (const float*)d_in[12];
    const float* sb  = (const float*)d_in[13];
    const float* pw  = (const float*)d_in[14];
    const float* pb  = (const float*)d_in[15];
    const float* fw  = (const float*)d_in[16];
    const float* fb  = (const float*)d_in[17];
    const float* fg  = (const float*)d_in[18];
    const float* fbe = (const float*)d_in[19];
    float* out = (float*)d_out;

    k_embzero<<<TT, 256>>>(tokens, embt);
    k_parser<<<dim3(64, TT), dim3(64, 4)>>>(c1w, c1b, bng, bnb, c2w);
    k_gatemask<<<64, 256>>>(c2b);

    // single persistent node for the whole 256-step recurrence
    k_scan<<<NB, 256>>>(wih, whh, bih, bhh, sw, sb, pw, pb);

    k_ffd<<<dim3(16, TT), 256>>>(fw, fb, fg, fbe, out);

    int rem = out_size - TT*BB*HH;
    if (rem > 0) {
        if (rem == TT*BB/4)
            k_maskb<<<64, 256>>>(tokens, (unsigned char*)out + (size_t)TT*BB*HH*4);
        else
            k_maskf<<<64, 256>>>(tokens, out + (size_t)TT*BB*HH, rem);
    }
}